// round 1
// baseline (speedup 1.0000x reference)
#include <cuda_runtime.h>
#include <math.h>

// Problem shape (fixed by the dataset):
//   t: [16, 256, 128, 128] fp32
//   w_reduce: [256, 1024], b_reduce: [256]
//   w_expand: [1024, 256], b_expand: [1024]
// Output: same shape as t.

#define NB   16
#define NC   256
#define NH   128
#define NW   128
#define NSQ  256
#define NC4  1024         // 4*C
#define IMG_F4 4096       // 128*128/4 float4 per (b,c) image

// Scratch (allocation-free rule: __device__ globals)
__device__ float g_means[NB * NC4];   // layout: [b][q*C + c]
__device__ float g_gate [NB * NC4];   // layout: [b][q*C + c]

// ---------------------------------------------------------------------------
// Kernel 1: per-(b,c) quadrant means.
// One CTA per image. 256 threads, 16 float4 loads each (fully coalesced).
// Thread's lane (tid&31) fixes column quadrant (lanes 0..15 = left half:
// col4 = tid&31 in [0,16) -> x < 64). Iteration k fixes row quadrant:
// rows covered are (tid>>5) + 8*k, so k<8 -> row<64 (top), k>=8 -> bottom.
// ---------------------------------------------------------------------------
__global__ __launch_bounds__(256) void quad_means_kernel(const float* __restrict__ t)
{
    const int img = blockIdx.x;                 // b*C + c
    const int tid = threadIdx.x;
    const float4* __restrict__ p =
        reinterpret_cast<const float4*>(t) + (size_t)img * IMG_F4;

    float topS = 0.f, botS = 0.f;
#pragma unroll
    for (int k = 0; k < 16; ++k) {
        float4 v = p[tid + k * 256];
        float s = (v.x + v.y) + (v.z + v.w);
        if (k < 8) topS += s; else botS += s;
    }

    const bool right = (tid & 31) >= 16;

    __shared__ float sm[4 * 256];
    sm[0 * 256 + tid] = right ? 0.f : topS;   // q0: top-left
    sm[1 * 256 + tid] = right ? topS : 0.f;   // q1: top-right
    sm[2 * 256 + tid] = right ? 0.f : botS;   // q2: bot-left
    sm[3 * 256 + tid] = right ? botS : 0.f;   // q3: bot-right
    __syncthreads();

#pragma unroll
    for (int st = 128; st > 0; st >>= 1) {
        if (tid < st) {
#pragma unroll
            for (int q = 0; q < 4; ++q)
                sm[q * 256 + tid] += sm[q * 256 + tid + st];
        }
        __syncthreads();
    }

    if (tid < 4) {
        const int b = img >> 8;       // img / 256
        const int c = img & 255;      // img % 256
        g_means[b * NC4 + tid * NC + c] = sm[tid * 256] * (1.0f / 4096.0f);
    }
}

// ---------------------------------------------------------------------------
// Kernel 2: tiny FC chain. One CTA per batch (16 CTAs, 256 threads).
//   z = mish(means @ w_reduce^T + b_reduce)      (256 outputs)
//   gate = sigmoid(z @ w_expand^T + b_expand)    (1024 outputs)
// ---------------------------------------------------------------------------
__global__ __launch_bounds__(256) void fc_kernel(
    const float* __restrict__ w_reduce, const float* __restrict__ b_reduce,
    const float* __restrict__ w_expand, const float* __restrict__ b_expand)
{
    const int b   = blockIdx.x;
    const int tid = threadIdx.x;

    __shared__ float sm_means[NC4];
    __shared__ float sm_z[NSQ];

    for (int i = tid; i < NC4; i += 256)
        sm_means[i] = g_means[b * NC4 + i];
    __syncthreads();

    // z[tid]
    {
        const float* __restrict__ wr = w_reduce + (size_t)tid * NC4;
        float acc = b_reduce[tid];
#pragma unroll 8
        for (int k = 0; k < NC4; ++k)
            acc = fmaf(sm_means[k], wr[k], acc);
        // mish(x) = x * tanh(softplus(x)); stable softplus
        float sp = (acc > 20.0f) ? acc : log1pf(expf(acc));
        sm_z[tid] = acc * tanhf(sp);
    }
    __syncthreads();

    // gate: 1024 outputs, 4 per thread
#pragma unroll
    for (int jj = 0; jj < 4; ++jj) {
        const int j = tid + jj * 256;
        const float* __restrict__ we = w_expand + (size_t)j * NSQ;
        float acc = b_expand[j];
#pragma unroll 8
        for (int k = 0; k < NSQ; ++k)
            acc = fmaf(sm_z[k], we[k], acc);
        g_gate[b * NC4 + j] = 1.0f / (1.0f + expf(-acc));
    }
}

// ---------------------------------------------------------------------------
// Kernel 3: out = t * gate[b, q(y,x)*C + c]. Flat float4 elementwise.
// Index bits: g (float4 idx) -> img = g>>12; within = g&4095;
// row = within>>5 (0..127); col4 = within&31 (0..31, quadrant split at 16).
// ---------------------------------------------------------------------------
__global__ __launch_bounds__(256) void apply_gate_kernel(
    const float* __restrict__ t, float* __restrict__ out)
{
    const int g = blockIdx.x * 256 + threadIdx.x;   // float4 index, exact grid

    const float4 v = reinterpret_cast<const float4*>(t)[g];

    const int within = g & (IMG_F4 - 1);
    const int img    = g >> 12;
    const int row    = within >> 5;
    const int col4   = within & 31;
    const int q      = ((row >= 64) ? 2 : 0) | ((col4 >= 16) ? 1 : 0);
    const int b      = img >> 8;
    const int c      = img & 255;

    const float gv = __ldg(&g_gate[b * NC4 + q * NC + c]);

    float4 o;
    o.x = v.x * gv; o.y = v.y * gv; o.z = v.z * gv; o.w = v.w * gv;
    reinterpret_cast<float4*>(out)[g] = o;
}

// ---------------------------------------------------------------------------
extern "C" void kernel_launch(void* const* d_in, const int* in_sizes, int n_in,
                              void* d_out, int out_size)
{
    const float* t        = (const float*)d_in[0];
    const float* w_reduce = (const float*)d_in[1];
    const float* b_reduce = (const float*)d_in[2];
    const float* w_expand = (const float*)d_in[3];
    const float* b_expand = (const float*)d_in[4];
    float* out            = (float*)d_out;

    // Pass 1: quadrant means (4096 CTAs)
    quad_means_kernel<<<NB * NC, 256>>>(t);

    // FC chain (16 CTAs)
    fc_kernel<<<NB, 256>>>(w_reduce, b_reduce, w_expand, b_expand);

    // Pass 2: gated multiply (16M float4 / 256 = 65536 CTAs)
    const int total_f4 = NB * NC * IMG_F4;   // 16777216
    apply_gate_kernel<<<total_f4 / 256, 256>>>(t, out);
}

// round 2
// speedup vs baseline: 2.6482x; 2.6482x over previous
#include <cuda_runtime.h>
#include <math.h>

// Problem shape (fixed by the dataset):
//   t: [16, 256, 128, 128] fp32
//   w_reduce: [256, 1024], b_reduce: [256]
//   w_expand: [1024, 256], b_expand: [1024]
// Output: same shape as t.

#define NB   16
#define NC   256
#define NSQ  256
#define NC4  1024         // 4*C
#define IMG_F4 4096       // 128*128/4 float4 per (b,c) image

// Scratch (allocation-free rule: __device__ globals)
__device__ float g_means[NB * NC4];   // layout: [b][q*C + c]
__device__ float g_z    [NB * NSQ];   // layout: [b][j]
__device__ float g_gate [NB * NC4];   // layout: [b][q*C + c]

// ---------------------------------------------------------------------------
// Kernel 1: per-(b,c) quadrant means. (Unchanged: 41.5us @ 82.9% DRAM.)
// One CTA per image. 256 threads, 16 float4 loads each (fully coalesced).
// ---------------------------------------------------------------------------
__global__ __launch_bounds__(256) void quad_means_kernel(const float* __restrict__ t)
{
    const int img = blockIdx.x;                 // b*C + c
    const int tid = threadIdx.x;
    const float4* __restrict__ p =
        reinterpret_cast<const float4*>(t) + (size_t)img * IMG_F4;

    float topS = 0.f, botS = 0.f;
#pragma unroll
    for (int k = 0; k < 16; ++k) {
        float4 v = p[tid + k * 256];
        float s = (v.x + v.y) + (v.z + v.w);
        if (k < 8) topS += s; else botS += s;
    }

    const bool right = (tid & 31) >= 16;

    __shared__ float sm[4 * 256];
    sm[0 * 256 + tid] = right ? 0.f : topS;   // q0: top-left
    sm[1 * 256 + tid] = right ? topS : 0.f;   // q1: top-right
    sm[2 * 256 + tid] = right ? 0.f : botS;   // q2: bot-left
    sm[3 * 256 + tid] = right ? botS : 0.f;   // q3: bot-right
    __syncthreads();

#pragma unroll
    for (int st = 128; st > 0; st >>= 1) {
        if (tid < st) {
#pragma unroll
            for (int q = 0; q < 4; ++q)
                sm[q * 256 + tid] += sm[q * 256 + tid + st];
        }
        __syncthreads();
    }

    if (tid < 4) {
        const int b = img >> 8;       // img / 256
        const int c = img & 255;      // img % 256
        g_means[b * NC4 + tid * NC + c] = sm[tid * 256] * (1.0f / 4096.0f);
    }
}

// ---------------------------------------------------------------------------
// Kernel 2a: z = mish(means @ w_reduce^T + b_reduce)
// Grid (16, 8): batch x part. Each CTA: 8 warps x 4 outputs = 32 outputs.
// Each warp computes one 1024-dot: lane reads float4 at [lane + 32*i],
// i=0..7 — fully coalesced 128B lines — then butterfly-reduces.
// ---------------------------------------------------------------------------
__global__ __launch_bounds__(256) void fc1_kernel(
    const float* __restrict__ w_reduce, const float* __restrict__ b_reduce)
{
    const int b    = blockIdx.x;
    const int part = blockIdx.y;          // 0..7
    const int tid  = threadIdx.x;
    const int warp = tid >> 5;
    const int lane = tid & 31;

    __shared__ float4 sm_m[256];          // means[b] as 256 float4
    {
        const float4* __restrict__ mp =
            reinterpret_cast<const float4*>(g_means + b * NC4);
        sm_m[tid] = mp[tid];
    }
    __syncthreads();

#pragma unroll
    for (int jj = 0; jj < 4; ++jj) {
        const int j = part * 32 + warp * 4 + jj;
        const float4* __restrict__ w =
            reinterpret_cast<const float4*>(w_reduce + (size_t)j * NC4);
        float acc = 0.f;
#pragma unroll
        for (int i = 0; i < 8; ++i) {
            float4 wv = w[lane + 32 * i];
            float4 mv = sm_m[lane + 32 * i];
            acc += wv.x * mv.x + wv.y * mv.y + wv.z * mv.z + wv.w * mv.w;
        }
#pragma unroll
        for (int o = 16; o > 0; o >>= 1)
            acc += __shfl_xor_sync(0xFFFFFFFFu, acc, o);
        if (lane == 0) {
            acc += b_reduce[j];
            float sp = (acc > 20.0f) ? acc : log1pf(expf(acc));
            g_z[b * NSQ + j] = acc * tanhf(sp);
        }
    }
}

// ---------------------------------------------------------------------------
// Kernel 2b: gate = sigmoid(z @ w_expand^T + b_expand)
// Grid (16, 8). Each CTA: 8 warps x 16 outputs = 128 outputs.
// Each warp: one 256-dot = 2 coalesced float4 loads per lane + reduce.
// ---------------------------------------------------------------------------
__global__ __launch_bounds__(256) void fc2_kernel(
    const float* __restrict__ w_expand, const float* __restrict__ b_expand)
{
    const int b    = blockIdx.x;
    const int part = blockIdx.y;          // 0..7
    const int tid  = threadIdx.x;
    const int warp = tid >> 5;
    const int lane = tid & 31;

    __shared__ float4 sm_z[64];           // z[b] as 64 float4
    if (tid < 64)
        sm_z[tid] = reinterpret_cast<const float4*>(g_z + b * NSQ)[tid];
    __syncthreads();

#pragma unroll
    for (int jj = 0; jj < 16; ++jj) {
        const int j = part * 128 + warp * 16 + jj;
        const float4* __restrict__ w =
            reinterpret_cast<const float4*>(w_expand + (size_t)j * NSQ);
        float acc = 0.f;
#pragma unroll
        for (int i = 0; i < 2; ++i) {
            float4 wv = w[lane + 32 * i];
            float4 zv = sm_z[lane + 32 * i];
            acc += wv.x * zv.x + wv.y * zv.y + wv.z * zv.z + wv.w * zv.w;
        }
#pragma unroll
        for (int o = 16; o > 0; o >>= 1)
            acc += __shfl_xor_sync(0xFFFFFFFFu, acc, o);
        if (lane == 0) {
            acc += b_expand[j];
            g_gate[b * NC4 + j] = 1.0f / (1.0f + expf(-acc));
        }
    }
}

// ---------------------------------------------------------------------------
// Kernel 3: out = t * gate[b, q(y,x)*C + c]. Flat float4 elementwise.
// ---------------------------------------------------------------------------
__global__ __launch_bounds__(256) void apply_gate_kernel(
    const float* __restrict__ t, float* __restrict__ out)
{
    const int g = blockIdx.x * 256 + threadIdx.x;   // float4 index, exact grid

    const float4 v = reinterpret_cast<const float4*>(t)[g];

    const int within = g & (IMG_F4 - 1);
    const int img    = g >> 12;
    const int row    = within >> 5;
    const int col4   = within & 31;
    const int q      = ((row >= 64) ? 2 : 0) | ((col4 >= 16) ? 1 : 0);
    const int b      = img >> 8;
    const int c      = img & 255;

    const float gv = __ldg(&g_gate[b * NC4 + q * NC + c]);

    float4 o;
    o.x = v.x * gv; o.y = v.y * gv; o.z = v.z * gv; o.w = v.w * gv;
    reinterpret_cast<float4*>(out)[g] = o;
}

// ---------------------------------------------------------------------------
extern "C" void kernel_launch(void* const* d_in, const int* in_sizes, int n_in,
                              void* d_out, int out_size)
{
    const float* t        = (const float*)d_in[0];
    const float* w_reduce = (const float*)d_in[1];
    const float* b_reduce = (const float*)d_in[2];
    const float* w_expand = (const float*)d_in[3];
    const float* b_expand = (const float*)d_in[4];
    float* out            = (float*)d_out;

    // Pass 1: quadrant means (4096 CTAs) — measured 41.5us @ 82.9% DRAM
    quad_means_kernel<<<NB * NC, 256>>>(t);

    // FC chain — coalesced warp-per-output
    fc1_kernel<<<dim3(NB, 8), 256>>>(w_reduce, b_reduce);
    fc2_kernel<<<dim3(NB, 8), 256>>>(w_expand, b_expand);

    // Pass 2: gated multiply (16M float4 / 256 = 65536 CTAs)
    const int total_f4 = NB * NC * IMG_F4;   // 16777216
    apply_gate_kernel<<<total_f4 / 256, 256>>>(t, out);
}

// round 3
// speedup vs baseline: 2.6741x; 1.0098x over previous
#include <cuda_runtime.h>
#include <math.h>

// Problem shape (fixed by the dataset):
//   t: [16, 256, 128, 128] fp32
//   w_reduce: [256, 1024], b_reduce: [256]
//   w_expand: [1024, 256], b_expand: [1024]
// Output: same shape as t.

#define NB   16
#define NC   256
#define NSQ  256
#define NC4  1024         // 4*C
#define IMG_F4 4096       // 128*128/4 float4 per (b,c) image

// Scratch (allocation-free rule: __device__ globals)
__device__ float g_means[NB * NC4];   // layout: [b][q*C + c]
__device__ float g_z    [NB * NSQ];   // layout: [b][j]
__device__ float g_gate [NB * NC4];   // layout: [b][q*C + c]

// ---------------------------------------------------------------------------
// Kernel 1: per-(b,c) quadrant means. (Measured 41.5us @ 82.9% DRAM — keep.)
// ---------------------------------------------------------------------------
__global__ __launch_bounds__(256) void quad_means_kernel(const float* __restrict__ t)
{
    const int img = blockIdx.x;                 // b*C + c
    const int tid = threadIdx.x;
    const float4* __restrict__ p =
        reinterpret_cast<const float4*>(t) + (size_t)img * IMG_F4;

    float topS = 0.f, botS = 0.f;
#pragma unroll
    for (int k = 0; k < 16; ++k) {
        float4 v = p[tid + k * 256];
        float s = (v.x + v.y) + (v.z + v.w);
        if (k < 8) topS += s; else botS += s;
    }

    const bool right = (tid & 31) >= 16;

    __shared__ float sm[4 * 256];
    sm[0 * 256 + tid] = right ? 0.f : topS;   // q0: top-left
    sm[1 * 256 + tid] = right ? topS : 0.f;   // q1: top-right
    sm[2 * 256 + tid] = right ? 0.f : botS;   // q2: bot-left
    sm[3 * 256 + tid] = right ? botS : 0.f;   // q3: bot-right
    __syncthreads();

#pragma unroll
    for (int st = 128; st > 0; st >>= 1) {
        if (tid < st) {
#pragma unroll
            for (int q = 0; q < 4; ++q)
                sm[q * 256 + tid] += sm[q * 256 + tid + st];
        }
        __syncthreads();
    }

    if (tid < 4) {
        const int b = img >> 8;
        const int c = img & 255;
        g_means[b * NC4 + tid * NC + c] = sm[tid * 256] * (1.0f / 4096.0f);
    }
}

// ---------------------------------------------------------------------------
// Kernel 2a: z = mish(means @ w_reduce^T + b_reduce), all batches per CTA.
// Grid 32 CTAs x 256 thr. Warp w owns output j = cta*8 + w. Its w_reduce row
// (1024 fp32) is loaded ONCE into registers (8 coalesced float4 per lane),
// then dotted against all 16 batches' means held in shared (64KB).
// Every weight byte is read exactly once across the grid.
// ---------------------------------------------------------------------------
__global__ __launch_bounds__(256) void fc1_kernel(
    const float* __restrict__ w_reduce, const float* __restrict__ b_reduce)
{
    const int tid  = threadIdx.x;
    const int warp = tid >> 5;
    const int lane = tid & 31;

    __shared__ float4 sm_m[NB * 256];     // all means: 16 x 1024 fp32 = 64KB
    {
        const float4* __restrict__ mp = reinterpret_cast<const float4*>(g_means);
#pragma unroll
        for (int i = 0; i < 16; ++i)
            sm_m[tid + i * 256] = mp[tid + i * 256];
    }
    __syncthreads();

    const int j = blockIdx.x * 8 + warp;
    const float4* __restrict__ w =
        reinterpret_cast<const float4*>(w_reduce + (size_t)j * NC4);

    float4 wr[8];
#pragma unroll
    for (int i = 0; i < 8; ++i)
        wr[i] = w[lane + 32 * i];

    const float bj = b_reduce[j];

#pragma unroll
    for (int b = 0; b < NB; ++b) {
        float acc = 0.f;
#pragma unroll
        for (int i = 0; i < 8; ++i) {
            float4 mv = sm_m[b * 256 + lane + 32 * i];
            acc += wr[i].x * mv.x + wr[i].y * mv.y + wr[i].z * mv.z + wr[i].w * mv.w;
        }
#pragma unroll
        for (int o = 16; o > 0; o >>= 1)
            acc += __shfl_xor_sync(0xFFFFFFFFu, acc, o);
        if (lane == 0) {
            float x = acc + bj;
            float sp = (x > 20.0f) ? x : log1pf(expf(x));
            g_z[b * NSQ + j] = x * tanhf(sp);
        }
    }
}

// ---------------------------------------------------------------------------
// Kernel 2b: gate = sigmoid(z @ w_expand^T + b_expand), all batches per CTA.
// Grid 32 CTAs x 256 thr. Warp w owns 4 outputs j = cta*32 + w*4 + jj.
// Each row (256 fp32) loaded once (2 float4/lane), dotted vs 16 batches'
// z in shared (16KB). Weights read exactly once across the grid.
// ---------------------------------------------------------------------------
__global__ __launch_bounds__(256) void fc2_kernel(
    const float* __restrict__ w_expand, const float* __restrict__ b_expand)
{
    const int tid  = threadIdx.x;
    const int warp = tid >> 5;
    const int lane = tid & 31;

    __shared__ float4 sm_z[NB * 64];      // all z: 16 x 256 fp32 = 16KB
    {
        const float4* __restrict__ zp = reinterpret_cast<const float4*>(g_z);
#pragma unroll
        for (int i = 0; i < 4; ++i)
            sm_z[tid + i * 256] = zp[tid + i * 256];
    }
    __syncthreads();

#pragma unroll
    for (int jj = 0; jj < 4; ++jj) {
        const int j = blockIdx.x * 32 + warp * 4 + jj;
        const float4* __restrict__ w =
            reinterpret_cast<const float4*>(w_expand + (size_t)j * NSQ);
        float4 w0 = w[lane];
        float4 w1 = w[lane + 32];
        const float bj = b_expand[j];

#pragma unroll
        for (int b = 0; b < NB; ++b) {
            float4 z0 = sm_z[b * 64 + lane];
            float4 z1 = sm_z[b * 64 + lane + 32];
            float acc = w0.x * z0.x + w0.y * z0.y + w0.z * z0.z + w0.w * z0.w
                      + w1.x * z1.x + w1.y * z1.y + w1.z * z1.z + w1.w * z1.w;
#pragma unroll
            for (int o = 16; o > 0; o >>= 1)
                acc += __shfl_xor_sync(0xFFFFFFFFu, acc, o);
            if (lane == 0)
                g_gate[b * NC4 + j] = 1.0f / (1.0f + expf(-acc - bj));
        }
    }
}

// ---------------------------------------------------------------------------
// Kernel 3: out = t * gate. 4 float4 per thread, strided by 256 within a
// 1024-float4 block. 1024 | 4096 so a CTA never crosses an image; the four
// accesses of one thread share (b, c, quadrant): rows span a 32-aligned
// 32-row window (same vertical half), col4 = tid&31 fixed (same horizontal
// half). Gate load + index math once per 4 elements; 4 loads in flight.
// ---------------------------------------------------------------------------
__global__ __launch_bounds__(256) void apply_gate_kernel(
    const float* __restrict__ t, float* __restrict__ out)
{
    const int base = blockIdx.x * 1024 + threadIdx.x;   // float4 index

    const int img    = base >> 12;
    const int within = base & (IMG_F4 - 1);
    const int row    = within >> 5;
    const int col4   = within & 31;
    const int q      = ((row >= 64) ? 2 : 0) | ((col4 >= 16) ? 1 : 0);
    const int b      = img >> 8;
    const int c      = img & 255;

    const float gv = __ldg(&g_gate[b * NC4 + q * NC + c]);

    const float4* __restrict__ tp = reinterpret_cast<const float4*>(t);
    float4* __restrict__ op       = reinterpret_cast<float4*>(out);

    float4 v0 = __ldcs(tp + base);
    float4 v1 = __ldcs(tp + base + 256);
    float4 v2 = __ldcs(tp + base + 512);
    float4 v3 = __ldcs(tp + base + 768);

    v0.x *= gv; v0.y *= gv; v0.z *= gv; v0.w *= gv;
    v1.x *= gv; v1.y *= gv; v1.z *= gv; v1.w *= gv;
    v2.x *= gv; v2.y *= gv; v2.z *= gv; v2.w *= gv;
    v3.x *= gv; v3.y *= gv; v3.z *= gv; v3.w *= gv;

    __stcs(op + base,       v0);
    __stcs(op + base + 256, v1);
    __stcs(op + base + 512, v2);
    __stcs(op + base + 768, v3);
}

// ---------------------------------------------------------------------------
extern "C" void kernel_launch(void* const* d_in, const int* in_sizes, int n_in,
                              void* d_out, int out_size)
{
    const float* t        = (const float*)d_in[0];
    const float* w_reduce = (const float*)d_in[1];
    const float* b_reduce = (const float*)d_in[2];
    const float* w_expand = (const float*)d_in[3];
    const float* b_expand = (const float*)d_in[4];
    float* out            = (float*)d_out;

    // Pass 1: quadrant means (4096 CTAs) — measured 41.5us @ 82.9% DRAM
    quad_means_kernel<<<NB * NC, 256>>>(t);

    // FC chain — weights read exactly once across the grid
    fc1_kernel<<<32, 256>>>(w_reduce, b_reduce);
    fc2_kernel<<<32, 256>>>(w_expand, b_expand);

    // Pass 2: gated multiply. 16M float4 / (256 thr * 4 f4) = 16384 CTAs
    const int total_f4 = NB * NC * IMG_F4;   // 16777216
    apply_gate_kernel<<<total_f4 / 1024, 256>>>(t, out);
}

// round 4
// speedup vs baseline: 2.6929x; 1.0070x over previous
#include <cuda_runtime.h>
#include <math.h>

// Problem shape (fixed by the dataset):
//   t: [16, 256, 128, 128] fp32
//   w_reduce: [256, 1024], b_reduce: [256]
//   w_expand: [1024, 256], b_expand: [1024]
// Output: same shape as t.

#define NB   16
#define NC   256
#define NSQ  256
#define NC4  1024         // 4*C
#define IMG_F4 4096       // 128*128/4 float4 per (b,c) image

// Scratch (allocation-free rule: __device__ globals)
__device__ float g_means[NB * NC4];   // layout: [b][q*C + c]
__device__ float g_z    [NB * NSQ];   // layout: [b][j]
__device__ float g_gate [NB * NC4];   // layout: [b][q*C + c]

// ---------------------------------------------------------------------------
// Kernel 1: per-(b,c) quadrant means. (Measured 41.5us @ 82.9% DRAM — keep.)
// ---------------------------------------------------------------------------
__global__ __launch_bounds__(256) void quad_means_kernel(const float* __restrict__ t)
{
    const int img = blockIdx.x;                 // b*C + c
    const int tid = threadIdx.x;
    const float4* __restrict__ p =
        reinterpret_cast<const float4*>(t) + (size_t)img * IMG_F4;

    float topS = 0.f, botS = 0.f;
#pragma unroll
    for (int k = 0; k < 16; ++k) {
        float4 v = p[tid + k * 256];
        float s = (v.x + v.y) + (v.z + v.w);
        if (k < 8) topS += s; else botS += s;
    }

    const bool right = (tid & 31) >= 16;

    __shared__ float sm[4 * 256];
    sm[0 * 256 + tid] = right ? 0.f : topS;   // q0: top-left
    sm[1 * 256 + tid] = right ? topS : 0.f;   // q1: top-right
    sm[2 * 256 + tid] = right ? 0.f : botS;   // q2: bot-left
    sm[3 * 256 + tid] = right ? botS : 0.f;   // q3: bot-right
    __syncthreads();

#pragma unroll
    for (int st = 128; st > 0; st >>= 1) {
        if (tid < st) {
#pragma unroll
            for (int q = 0; q < 4; ++q)
                sm[q * 256 + tid] += sm[q * 256 + tid + st];
        }
        __syncthreads();
    }

    if (tid < 4) {
        const int b = img >> 8;
        const int c = img & 255;
        g_means[b * NC4 + tid * NC + c] = sm[tid * 256] * (1.0f / 4096.0f);
    }
}

// ---------------------------------------------------------------------------
// Kernel 2a: z = mish(means @ w_reduce^T + b_reduce), all batches per CTA.
// Grid 32 CTAs x 256 thr. Warp w owns output j = cta*8 + w. Its w_reduce row
// (1024 fp32) is loaded ONCE into registers (8 coalesced float4 per lane),
// then dotted against all 16 batches' means held in shared (64KB).
// Every weight byte is read exactly once across the grid.
// ---------------------------------------------------------------------------
__global__ __launch_bounds__(256) void fc1_kernel(
    const float* __restrict__ w_reduce, const float* __restrict__ b_reduce)
{
    const int tid  = threadIdx.x;
    const int warp = tid >> 5;
    const int lane = tid & 31;

    __shared__ float4 sm_m[NB * 256];     // all means: 16 x 1024 fp32 = 64KB
    {
        const float4* __restrict__ mp = reinterpret_cast<const float4*>(g_means);
#pragma unroll
        for (int i = 0; i < 16; ++i)
            sm_m[tid + i * 256] = mp[tid + i * 256];
    }
    __syncthreads();

    const int j = blockIdx.x * 8 + warp;
    const float4* __restrict__ w =
        reinterpret_cast<const float4*>(w_reduce + (size_t)j * NC4);

    float4 wr[8];
#pragma unroll
    for (int i = 0; i < 8; ++i)
        wr[i] = w[lane + 32 * i];

    const float bj = b_reduce[j];

#pragma unroll
    for (int b = 0; b < NB; ++b) {
        float acc = 0.f;
#pragma unroll
        for (int i = 0; i < 8; ++i) {
            float4 mv = sm_m[b * 256 + lane + 32 * i];
            acc += wr[i].x * mv.x + wr[i].y * mv.y + wr[i].z * mv.z + wr[i].w * mv.w;
        }
#pragma unroll
        for (int o = 16; o > 0; o >>= 1)
            acc += __shfl_xor_sync(0xFFFFFFFFu, acc, o);
        if (lane == 0) {
            float x = acc + bj;
            float sp = (x > 20.0f) ? x : log1pf(expf(x));
            g_z[b * NSQ + j] = x * tanhf(sp);
        }
    }
}

// ---------------------------------------------------------------------------
// Kernel 2b: gate = sigmoid(z @ w_expand^T + b_expand), all batches per CTA.
// Grid 32 CTAs x 256 thr. Warp w owns 4 outputs j = cta*32 + w*4 + jj.
// Each row (256 fp32) loaded once (2 float4/lane), dotted vs 16 batches'
// z in shared (16KB). Weights read exactly once across the grid.
// ---------------------------------------------------------------------------
__global__ __launch_bounds__(256) void fc2_kernel(
    const float* __restrict__ w_expand, const float* __restrict__ b_expand)
{
    const int tid  = threadIdx.x;
    const int warp = tid >> 5;
    const int lane = tid & 31;

    __shared__ float4 sm_z[NB * 64];      // all z: 16 x 256 fp32 = 16KB
    {
        const float4* __restrict__ zp = reinterpret_cast<const float4*>(g_z);
#pragma unroll
        for (int i = 0; i < 4; ++i)
            sm_z[tid + i * 256] = zp[tid + i * 256];
    }
    __syncthreads();

#pragma unroll
    for (int jj = 0; jj < 4; ++jj) {
        const int j = blockIdx.x * 32 + warp * 4 + jj;
        const float4* __restrict__ w =
            reinterpret_cast<const float4*>(w_expand + (size_t)j * NSQ);
        float4 w0 = w[lane];
        float4 w1 = w[lane + 32];
        const float bj = b_expand[j];

#pragma unroll
        for (int b = 0; b < NB; ++b) {
            float4 z0 = sm_z[b * 64 + lane];
            float4 z1 = sm_z[b * 64 + lane + 32];
            float acc = w0.x * z0.x + w0.y * z0.y + w0.z * z0.z + w0.w * z0.w
                      + w1.x * z1.x + w1.y * z1.y + w1.z * z1.z + w1.w * z1.w;
#pragma unroll
            for (int o = 16; o > 0; o >>= 1)
                acc += __shfl_xor_sync(0xFFFFFFFFu, acc, o);
            if (lane == 0)
                g_gate[b * NC4 + j] = 1.0f / (1.0f + expf(-acc - bj));
        }
    }
}

// ---------------------------------------------------------------------------
// Kernel 3: out = t * gate. 4 float4 per thread, strided by 256 within a
// 1024-float4 block. 1024 | 4096 so a CTA never crosses an image; the four
// accesses of one thread share (b, c, quadrant): rows span a 32-aligned
// 32-row window (same vertical half), col4 = tid&31 fixed (same horizontal
// half). Gate load + index math once per 4 elements; 4 loads in flight.
// ---------------------------------------------------------------------------
__global__ __launch_bounds__(256) void apply_gate_kernel(
    const float* __restrict__ t, float* __restrict__ out)
{
    const int base = blockIdx.x * 1024 + threadIdx.x;   // float4 index

    const int img    = base >> 12;
    const int within = base & (IMG_F4 - 1);
    const int row    = within >> 5;
    const int col4   = within & 31;
    const int q      = ((row >= 64) ? 2 : 0) | ((col4 >= 16) ? 1 : 0);
    const int b      = img >> 8;
    const int c      = img & 255;

    const float gv = __ldg(&g_gate[b * NC4 + q * NC + c]);

    const float4* __restrict__ tp = reinterpret_cast<const float4*>(t);
    float4* __restrict__ op       = reinterpret_cast<float4*>(out);

    float4 v0 = __ldcs(tp + base);
    float4 v1 = __ldcs(tp + base + 256);
    float4 v2 = __ldcs(tp + base + 512);
    float4 v3 = __ldcs(tp + base + 768);

    v0.x *= gv; v0.y *= gv; v0.z *= gv; v0.w *= gv;
    v1.x *= gv; v1.y *= gv; v1.z *= gv; v1.w *= gv;
    v2.x *= gv; v2.y *= gv; v2.z *= gv; v2.w *= gv;
    v3.x *= gv; v3.y *= gv; v3.z *= gv; v3.w *= gv;

    __stcs(op + base,       v0);
    __stcs(op + base + 256, v1);
    __stcs(op + base + 512, v2);
    __stcs(op + base + 768, v3);
}

// ---------------------------------------------------------------------------
extern "C" void kernel_launch(void* const* d_in, const int* in_sizes, int n_in,
                              void* d_out, int out_size)
{
    const float* t        = (const float*)d_in[0];
    const float* w_reduce = (const float*)d_in[1];
    const float* b_reduce = (const float*)d_in[2];
    const float* w_expand = (const float*)d_in[3];
    const float* b_expand = (const float*)d_in[4];
    float* out            = (float*)d_out;

    // Pass 1: quadrant means (4096 CTAs) — measured 41.5us @ 82.9% DRAM
    quad_means_kernel<<<NB * NC, 256>>>(t);

    // FC chain — weights read exactly once across the grid
    fc1_kernel<<<32, 256>>>(w_reduce, b_reduce);
    fc2_kernel<<<32, 256>>>(w_expand, b_expand);

    // Pass 2: gated multiply. 16M float4 / (256 thr * 4 f4) = 16384 CTAs
    const int total_f4 = NB * NC * IMG_F4;   // 16777216
    apply_gate_kernel<<<total_f4 / 1024, 256>>>(t, out);
}